// round 10
// baseline (speedup 1.0000x reference)
#include <cuda_runtime.h>
#include <cuda_fp16.h>
#include <cstdint>

#define L_SEQ 2048
#define BATCH 2
#define EMB   256
#define NH    8
#define HD    32
#define NROWS (L_SEQ*BATCH)   // 4096
#define KT    128             // attention key tile
// SCALE * log2(e): softmax done in exp2 domain
#define SCALE_LOG2E 0.25500927171408637f

// Scratch (allocation-free), fp16:
__device__ __half2 g_Wh[4*EMB*(EMB/2)];          // fp16 copies of Wq/Wk/Wv/Wp
__device__ __half2 g_Q[BATCH*NH*L_SEQ*(HD/2)];   // [b][h][l][d/2], pre-scaled
__device__ __half  g_K[BATCH*NH*HD*L_SEQ];       // [b][h][d][l]
__device__ __half2 g_V[BATCH*NH*L_SEQ*(HD/2)];   // [b][h][l][d/2]

// ---------------------------------------------------------------------------
__device__ __forceinline__ uint32_t pack2(float x, float y) {
    __half2 h = __floats2half2_rn(x, y);
    return *reinterpret_cast<uint32_t*>(&h);
}
__device__ __forceinline__ float ex2(float x) {
    float y; asm("ex2.approx.ftz.f32 %0, %1;" : "=f"(y) : "f"(x)); return y;
}
__device__ __forceinline__ void mma_f16(float c[4],
    uint32_t a0, uint32_t a1, uint32_t a2, uint32_t a3,
    uint32_t b0, uint32_t b1)
{
    asm volatile(
        "mma.sync.aligned.m16n8k16.row.col.f32.f16.f16.f32 "
        "{%0,%1,%2,%3},{%4,%5,%6,%7},{%8,%9},{%0,%1,%2,%3};"
        : "+f"(c[0]), "+f"(c[1]), "+f"(c[2]), "+f"(c[3])
        : "r"(a0), "r"(a1), "r"(a2), "r"(a3), "r"(b0), "r"(b1));
}
__device__ __forceinline__ void ldsm4(uint32_t r[4], uint32_t addr) {
    asm volatile("ldmatrix.sync.aligned.m8n8.x4.shared.b16 {%0,%1,%2,%3},[%4];"
        : "=r"(r[0]), "=r"(r[1]), "=r"(r[2]), "=r"(r[3]) : "r"(addr));
}
__device__ __forceinline__ void ldsm4t(uint32_t r[4], uint32_t addr) {
    asm volatile("ldmatrix.sync.aligned.m8n8.x4.trans.shared.b16 {%0,%1,%2,%3},[%4];"
        : "=r"(r[0]), "=r"(r[1]), "=r"(r[2]), "=r"(r[3]) : "r"(addr));
}
__device__ __forceinline__ void cpa16(uint32_t dst, const void* src) {
    asm volatile("cp.async.ca.shared.global [%0], [%1], 16;" :: "r"(dst), "l"(src));
}
__device__ __forceinline__ void cp_commit() {
    asm volatile("cp.async.commit_group;");
}
template<int N> __device__ __forceinline__ void cp_wait() {
    asm volatile("cp.async.wait_group %0;" :: "n"(N));
}

// ---------------------------------------------------------------------------
// prep: convert W0..W3 to fp16 AND initialize out with bias bp.
// grid 2560 x 256 thr: first 131072 items = W half2 converts,
// remaining 524288 items = out float2 init.
// ---------------------------------------------------------------------------
__global__ __launch_bounds__(256) void prep_kernel(
    const float* __restrict__ wq, const float* __restrict__ wk,
    const float* __restrict__ wv, const float* __restrict__ wp,
    const float* __restrict__ bp, float* __restrict__ out)
{
    int idx = blockIdx.x * 256 + threadIdx.x;
    if (idx < 131072) {
        int w = idx >> 15, i = idx & 32767;
        const float* src = (w == 0) ? wq : (w == 1) ? wk : (w == 2) ? wv : wp;
        float2 xv = *(const float2*)&src[2 * (size_t)i];
        g_Wh[(size_t)w * (EMB*(EMB/2)) + i] = __floats2half2_rn(xv.x, xv.y);
    } else {
        int j = idx - 131072;             // out float2 index
        int c0 = (2 * j) & 255;
        *(float2*)&out[2 * (size_t)j] = make_float2(bp[c0], bp[c0 + 1]);
    }
}

// ---------------------------------------------------------------------------
// QKV projection: C[4096,256] = X @ W + bias. X fp32 via register-prefetch
// double buffering; W fp16 via 3-stage cp.async. Tile 64x64, 128 thr.
// z = 0/1/2 -> Q (scaled) / K ([d][l]) / V.
// ---------------------------------------------------------------------------
__global__ __launch_bounds__(128) void proj_qkv_kernel(
    const float* __restrict__ Xq, const float* __restrict__ Xk,
    const float* __restrict__ Xv,
    const float* __restrict__ Bq, const float* __restrict__ Bk,
    const float* __restrict__ Bv)
{
    __shared__ __align__(16) __half Xs[2][64][40];   // 5120B/stage
    __shared__ __align__(16) __half Ws[3][32][72];   // 4608B/stage

    int z = blockIdx.z;
    const float* __restrict__ X    = (z == 0) ? Xq : (z == 1) ? Xk : Xv;
    const float* __restrict__ bias = (z == 0) ? Bq : (z == 1) ? Bk : Bv;
    const __half2* __restrict__ Wsrc = g_Wh + (size_t)z * (EMB*(EMB/2));

    int tid  = threadIdx.x;
    int lane = tid & 31, warp = tid >> 5;
    int gid  = lane >> 2, tig = lane & 3;
    int m0   = warp * 16;
    int rowBase = blockIdx.y * 64;
    int colBase = blockIdx.x * 64;

    uint32_t xs_base = (uint32_t)__cvta_generic_to_shared(&Xs[0][0][0]);
    uint32_t ws_base = (uint32_t)__cvta_generic_to_shared(&Ws[0][0][0]);

    auto fillW = [&](int s, int k0) {
        uint32_t wb = ws_base + s * 4608;
        #pragma unroll
        for (int i = tid; i < 256; i += 128) {
            int r = i >> 3, c = i & 7;
            cpa16(wb + r * 144 + c * 16,
                  Wsrc + (size_t)(k0 + r) * (EMB/2) + (colBase >> 1) + c * 4);
        }
    };
    auto ldgX = [&](float4 xr[4], int k0) {
        #pragma unroll
        for (int j = 0; j < 4; j++) {
            int cc = tid + 128 * j;
            int r = cc >> 3, c4 = cc & 7;
            xr[j] = *(const float4*)&X[(size_t)(rowBase + r) * EMB + k0 + c4 * 4];
        }
    };
    auto stsX = [&](float4 xr[4], int s) {
        #pragma unroll
        for (int j = 0; j < 4; j++) {
            int cc = tid + 128 * j;
            int r = cc >> 3, c4 = cc & 7;
            uint2 h;
            h.x = pack2(xr[j].x, xr[j].y);
            h.y = pack2(xr[j].z, xr[j].w);
            *(uint2*)&Xs[s][r][c4 * 4] = h;
        }
    };

    float cc[8][4];
    #pragma unroll
    for (int nn = 0; nn < 8; nn++)
        #pragma unroll
        for (int j = 0; j < 4; j++) cc[nn][j] = 0.f;

    fillW(0, 0);  cp_commit();
    fillW(1, 32); cp_commit();
    float4 xr[4];
    ldgX(xr, 0);

    for (int it = 0; it < 8; it++) {
        stsX(xr, it & 1);
        if (it < 7) ldgX(xr, (it + 1) * 32);
        if (it < 7) cp_wait<1>(); else cp_wait<0>();
        __syncthreads();
        if (it < 6) { fillW((it + 2) % 3, (it + 2) * 32); cp_commit(); }

        uint32_t xb = xs_base + (it & 1) * 5120;
        uint32_t wb = ws_base + (it % 3) * 4608;

        uint32_t a[2][4];
        #pragma unroll
        for (int kc = 0; kc < 2; kc++) {
            int m = lane >> 3;
            int row = m0 + (m & 1) * 8 + (lane & 7);
            int koff = kc * 16 + (m >> 1) * 8;
            ldsm4(a[kc], xb + row * 80 + koff * 2);
        }
        #pragma unroll
        for (int nn = 0; nn < 8; nn++) {
            uint32_t b[4];
            ldsm4t(b, wb + lane * 144 + nn * 16);
            mma_f16(cc[nn], a[0][0], a[0][1], a[0][2], a[0][3], b[0], b[1]);
            mma_f16(cc[nn], a[1][0], a[1][1], a[1][2], a[1][3], b[2], b[3]);
        }
    }

    // epilogue: scatter to g_Q / g_K / g_V
    int r_lo = rowBase + m0 + gid;
    int r_hi = r_lo + 8;
    #pragma unroll
    for (int nn = 0; nn < 8; nn++) {
        int c0 = colBase + nn * 8 + 2 * tig;
        float bv0 = bias[c0], bv1 = bias[c0 + 1];
        float v00 = cc[nn][0] + bv0, v01 = cc[nn][1] + bv1;   // row r_lo
        float v10 = cc[nn][2] + bv0, v11 = cc[nn][3] + bv1;   // row r_hi
        int h = (c0 >> 5) & 7, d = c0 & 31;
        int l0 = r_lo >> 1, b0i = r_lo & 1;     // row = l*B + b
        int l1 = r_hi >> 1, b1i = r_hi & 1;
        int bh0 = b0i * NH + h, bh1 = b1i * NH + h;
        if (z == 0) {
            g_Q[((size_t)bh0 * L_SEQ + l0) * (HD/2) + (d >> 1)] =
                __floats2half2_rn(v00 * SCALE_LOG2E, v01 * SCALE_LOG2E);
            g_Q[((size_t)bh1 * L_SEQ + l1) * (HD/2) + (d >> 1)] =
                __floats2half2_rn(v10 * SCALE_LOG2E, v11 * SCALE_LOG2E);
        } else if (z == 1) {
            g_K[((size_t)bh0 * HD + d    ) * L_SEQ + l0] = __float2half_rn(v00);
            g_K[((size_t)bh0 * HD + d + 1) * L_SEQ + l0] = __float2half_rn(v01);
            g_K[((size_t)bh1 * HD + d    ) * L_SEQ + l1] = __float2half_rn(v10);
            g_K[((size_t)bh1 * HD + d + 1) * L_SEQ + l1] = __float2half_rn(v11);
        } else {
            g_V[((size_t)bh0 * L_SEQ + l0) * (HD/2) + (d >> 1)] = __floats2half2_rn(v00, v01);
            g_V[((size_t)bh1 * L_SEQ + l1) * (HD/2) + (d >> 1)] = __floats2half2_rn(v10, v11);
        }
    }
}

// ---------------------------------------------------------------------------
// Flash attention + fused output projection.
// CTA = (b,h) x 64-query tile, 4 warps x 16 rows, 128-key tiles,
// 3-stage cp.async (dynamic smem), 1 barrier/iter.
// Epilogue: O (C-frags) @ Wp[h-slice] -> atomicAdd into out (bias pre-init).
// Stage: Ks [32][136] (8704B) + Vs [128][40] (10240B) = 18944B.
// Wp slice [32][264] halves (16896B) reuses stage-1 region after mainloop.
// ---------------------------------------------------------------------------
#define ATTN_STAGE 18944
#define ATTN_SMEM  (3*ATTN_STAGE)

__global__ __launch_bounds__(128) void attn_kernel(float* __restrict__ out)
{
    extern __shared__ __align__(16) char sm_attn[];

    int bh = blockIdx.y;
    int q0 = blockIdx.x * 64;
    int tid  = threadIdx.x;
    int lane = tid & 31, warp = tid >> 5;
    int gid  = lane >> 2, tig = lane & 3;
    int m0   = warp * 16;

    const __half2* __restrict__ Qh = g_Q + (size_t)bh * L_SEQ * (HD/2);
    const __half*  __restrict__ Kp = g_K + (size_t)bh * HD * L_SEQ;
    const __half*  __restrict__ Vp = (const __half*)(g_V + (size_t)bh * L_SEQ * (HD/2));

    uint32_t smb = (uint32_t)__cvta_generic_to_shared(sm_attn);

    auto fill = [&](int s, int kt) {
        uint32_t kb = smb + s * ATTN_STAGE;
        uint32_t vb = kb + 8704;
        #pragma unroll
        for (int i = tid; i < 512; i += 128) {       // Ks[d][key]
            int d = i >> 4, c = i & 15;
            cpa16(kb + d * 272 + c * 16, Kp + (size_t)d * L_SEQ + kt + c * 8);
        }
        #pragma unroll
        for (int i = tid; i < 512; i += 128) {       // Vs[key][d]
            int key = i >> 2, c = i & 3;
            cpa16(vb + key * 80 + c * 16, Vp + (size_t)(kt + key) * HD + c * 8);
        }
    };

    // Q A-fragments from gmem (reused for all key tiles)
    uint32_t aq[2][4];
    #pragma unroll
    for (int kc = 0; kc < 2; kc++) {
        aq[kc][0] = *(const uint32_t*)&Qh[(size_t)(q0 + m0 + gid    ) * (HD/2) + kc * 8 + tig    ];
        aq[kc][1] = *(const uint32_t*)&Qh[(size_t)(q0 + m0 + gid + 8) * (HD/2) + kc * 8 + tig    ];
        aq[kc][2] = *(const uint32_t*)&Qh[(size_t)(q0 + m0 + gid    ) * (HD/2) + kc * 8 + tig + 4];
        aq[kc][3] = *(const uint32_t*)&Qh[(size_t)(q0 + m0 + gid + 8) * (HD/2) + kc * 8 + tig + 4];
    }

    float m_lo = -1e30f, m_hi = -1e30f, l_lo = 0.f, l_hi = 0.f;
    float oc[4][4];
    #pragma unroll
    for (int nf = 0; nf < 4; nf++)
        #pragma unroll
        for (int j = 0; j < 4; j++) oc[nf][j] = 0.f;

    fill(0, 0);   cp_commit();
    fill(1, KT);  cp_commit();

    const int NIT = L_SEQ / KT;   // 16
    for (int it = 0; it < NIT; it++) {
        if (it < NIT - 1) cp_wait<1>(); else cp_wait<0>();
        __syncthreads();                      // all warps done with iter it-1
        if (it < NIT - 2) { fill((it + 2) % 3, (it + 2) * KT); cp_commit(); }

        uint32_t kb = smb + (it % 3) * ATTN_STAGE;
        uint32_t vb = kb + 8704;

        // ---- S = Q K^T (logits in log2 domain via Q scale) ----
        float sc[16][4];
        #pragma unroll
        for (int nn = 0; nn < 16; nn++) {
            sc[nn][0] = sc[nn][1] = sc[nn][2] = sc[nn][3] = 0.f;
            uint32_t b[4];
            ldsm4t(b, kb + lane * 272 + nn * 16);
            mma_f16(sc[nn], aq[0][0], aq[0][1], aq[0][2], aq[0][3], b[0], b[1]);
            mma_f16(sc[nn], aq[1][0], aq[1][1], aq[1][2], aq[1][3], b[2], b[3]);
        }

        // ---- online softmax (exp2 domain) ----
        float mx_lo = -1e30f, mx_hi = -1e30f;
        #pragma unroll
        for (int nn = 0; nn < 16; nn++) {
            mx_lo = fmaxf(mx_lo, fmaxf(sc[nn][0], sc[nn][1]));
            mx_hi = fmaxf(mx_hi, fmaxf(sc[nn][2], sc[nn][3]));
        }
        mx_lo = fmaxf(mx_lo, __shfl_xor_sync(0xffffffffu, mx_lo, 1));
        mx_lo = fmaxf(mx_lo, __shfl_xor_sync(0xffffffffu, mx_lo, 2));
        mx_hi = fmaxf(mx_hi, __shfl_xor_sync(0xffffffffu, mx_hi, 1));
        mx_hi = fmaxf(mx_hi, __shfl_xor_sync(0xffffffffu, mx_hi, 2));

        float mn_lo = fmaxf(m_lo, mx_lo), mn_hi = fmaxf(m_hi, mx_hi);
        float al_lo = ex2(m_lo - mn_lo), al_hi = ex2(m_hi - mn_hi);
        m_lo = mn_lo; m_hi = mn_hi;

        float sum_lo = 0.f, sum_hi = 0.f;
        #pragma unroll
        for (int nn = 0; nn < 16; nn++) {
            float p0 = ex2(sc[nn][0] - mn_lo);
            float p1 = ex2(sc[nn][1] - mn_lo);
            float p2 = ex2(sc[nn][2] - mn_hi);
            float p3 = ex2(sc[nn][3] - mn_hi);
            sum_lo += p0 + p1;  sum_hi += p2 + p3;
            sc[nn][0] = p0; sc[nn][1] = p1; sc[nn][2] = p2; sc[nn][3] = p3;
        }
        sum_lo += __shfl_xor_sync(0xffffffffu, sum_lo, 1);
        sum_lo += __shfl_xor_sync(0xffffffffu, sum_lo, 2);
        sum_hi += __shfl_xor_sync(0xffffffffu, sum_hi, 1);
        sum_hi += __shfl_xor_sync(0xffffffffu, sum_hi, 2);
        l_lo = l_lo * al_lo + sum_lo;
        l_hi = l_hi * al_hi + sum_hi;

        #pragma unroll
        for (int nf = 0; nf < 4; nf++) {
            oc[nf][0] *= al_lo; oc[nf][1] *= al_lo;
            oc[nf][2] *= al_hi; oc[nf][3] *= al_hi;
        }

        // ---- O += P V ----
        #pragma unroll
        for (int kg = 0; kg < 4; kg++) {
            uint32_t pA0 = pack2(sc[4*kg    ][0], sc[4*kg    ][1]);
            uint32_t pA1 = pack2(sc[4*kg    ][2], sc[4*kg    ][3]);
            uint32_t pA2 = pack2(sc[4*kg + 1][0], sc[4*kg + 1][1]);
            uint32_t pA3 = pack2(sc[4*kg + 1][2], sc[4*kg + 1][3]);
            uint32_t pB0 = pack2(sc[4*kg + 2][0], sc[4*kg + 2][1]);
            uint32_t pB1 = pack2(sc[4*kg + 2][2], sc[4*kg + 2][3]);
            uint32_t pB2 = pack2(sc[4*kg + 3][0], sc[4*kg + 3][1]);
            uint32_t pB3 = pack2(sc[4*kg + 3][2], sc[4*kg + 3][3]);
            #pragma unroll
            for (int nf = 0; nf < 4; nf++) {
                uint32_t v[4];
                ldsm4t(v, vb + (kg * 32 + lane) * 80 + nf * 16);
                mma_f16(oc[nf], pA0, pA1, pA2, pA3, v[0], v[1]);
                mma_f16(oc[nf], pB0, pB1, pB2, pB3, v[2], v[3]);
            }
        }
    }

    // ---- fused output projection: out += (O/l) @ Wp[h*32:(h+1)*32, :] ----
    int b = bh >> 3, h = bh & 7;
    uint32_t wpb = smb + ATTN_STAGE;   // reuse stage-1 region (dead after loop)
    const __half2* __restrict__ WpSrc =
        g_Wh + (size_t)3 * (EMB*(EMB/2)) + (size_t)(h * HD) * (EMB/2);
    // Wp slice: 32 rows x 256 halves, smem stride 528B (264 halves)
    #pragma unroll
    for (int i = tid; i < 1024; i += 128) {
        int r = i >> 5, c = i & 31;
        cpa16(wpb + r * 528 + c * 16, WpSrc + (size_t)r * (EMB/2) + c * 4);
    }
    cp_commit();

    // normalize O and pack into A-fragments (K-dim = 32 -> 2 k-steps)
    float inv_lo = 1.f / l_lo, inv_hi = 1.f / l_hi;
    uint32_t ao[2][4];
    #pragma unroll
    for (int kc = 0; kc < 2; kc++) {
        ao[kc][0] = pack2(oc[2*kc    ][0] * inv_lo, oc[2*kc    ][1] * inv_lo);
        ao[kc][1] = pack2(oc[2*kc    ][2] * inv_hi, oc[2*kc    ][3] * inv_hi);
        ao[kc][2] = pack2(oc[2*kc + 1][0] * inv_lo, oc[2*kc + 1][1] * inv_lo);
        ao[kc][3] = pack2(oc[2*kc + 1][2] * inv_hi, oc[2*kc + 1][3] * inv_hi);
    }

    cp_wait<0>();
    __syncthreads();   // Wp slice visible to all warps

    int or_lo = (q0 + m0 + gid) * BATCH + b;   // out row for r_lo
    int or_hi = or_lo + 8 * BATCH;             // out row for r_hi
    #pragma unroll
    for (int nn = 0; nn < 32; nn++) {
        float c[4] = {0.f, 0.f, 0.f, 0.f};
        uint32_t v[4];
        ldsm4t(v, wpb + lane * 528 + nn * 16);
        mma_f16(c, ao[0][0], ao[0][1], ao[0][2], ao[0][3], v[0], v[1]);
        mma_f16(c, ao[1][0], ao[1][1], ao[1][2], ao[1][3], v[2], v[3]);
        int c0 = nn * 8 + 2 * tig;
        atomicAdd(&out[(size_t)or_lo * EMB + c0    ], c[0]);
        atomicAdd(&out[(size_t)or_lo * EMB + c0 + 1], c[1]);
        atomicAdd(&out[(size_t)or_hi * EMB + c0    ], c[2]);
        atomicAdd(&out[(size_t)or_hi * EMB + c0 + 1], c[3]);
    }
}

// ---------------------------------------------------------------------------
extern "C" void kernel_launch(void* const* d_in, const int* in_sizes, int n_in,
                              void* d_out, int out_size)
{
    const float* query = (const float*)d_in[0];
    const float* key_  = (const float*)d_in[1];
    const float* value = (const float*)d_in[2];
    const float* Wq = (const float*)d_in[3];
    const float* bq = (const float*)d_in[4];
    const float* Wk = (const float*)d_in[5];
    const float* bk = (const float*)d_in[6];
    const float* Wv = (const float*)d_in[7];
    const float* bv = (const float*)d_in[8];
    const float* Wp = (const float*)d_in[9];
    const float* bp = (const float*)d_in[10];
    float* out = (float*)d_out;

    // idempotent, host-side, capture-safe; no static guard
    cudaFuncSetAttribute(attn_kernel,
        cudaFuncAttributeMaxDynamicSharedMemorySize, ATTN_SMEM);

    prep_kernel<<<2560, 256>>>(Wq, Wk, Wv, Wp, bp, out);

    dim3 gridQKV(EMB / 64, NROWS / 64, 3);    // (4, 64, 3)
    proj_qkv_kernel<<<gridQKV, 128>>>(query, key_, value, bq, bk, bv);

    dim3 gridA(L_SEQ / 64, BATCH * NH);       // (32, 16)
    attn_kernel<<<gridA, 128, ATTN_SMEM>>>(out);
}

// round 16
// speedup vs baseline: 1.0956x; 1.0956x over previous
#include <cuda_runtime.h>
#include <cuda_fp16.h>
#include <cstdint>

#define L_SEQ 2048
#define BATCH 2
#define EMB   256
#define NH    8
#define HD    32
#define NROWS (L_SEQ*BATCH)   // 4096
#define KT    128             // attention key tile
#define QT    128             // attention query tile (8 warps x 16 rows)
// SCALE * log2(e): softmax done in exp2 domain
#define SCALE_LOG2E 0.25500927171408637f

// Scratch (allocation-free), fp16:
__device__ __half2 g_Q[BATCH*NH*L_SEQ*(HD/2)];   // [b][h][l][d/2], pre-scaled
__device__ __half  g_K[BATCH*NH*HD*L_SEQ];       // [b][h][d][l]
__device__ __half2 g_V[BATCH*NH*L_SEQ*(HD/2)];   // [b][h][l][d/2]
__device__ __half2 g_AO[NROWS*(EMB/2)];          // [l][b][e/2]

// ---------------------------------------------------------------------------
__device__ __forceinline__ uint32_t pack2(float x, float y) {
    __half2 h = __floats2half2_rn(x, y);
    return *reinterpret_cast<uint32_t*>(&h);
}
__device__ __forceinline__ float ex2(float x) {
    float y; asm("ex2.approx.ftz.f32 %0, %1;" : "=f"(y) : "f"(x)); return y;
}
__device__ __forceinline__ void mma_f16(float c[4],
    uint32_t a0, uint32_t a1, uint32_t a2, uint32_t a3,
    uint32_t b0, uint32_t b1)
{
    asm volatile(
        "mma.sync.aligned.m16n8k16.row.col.f32.f16.f16.f32 "
        "{%0,%1,%2,%3},{%4,%5,%6,%7},{%8,%9},{%0,%1,%2,%3};"
        : "+f"(c[0]), "+f"(c[1]), "+f"(c[2]), "+f"(c[3])
        : "r"(a0), "r"(a1), "r"(a2), "r"(a3), "r"(b0), "r"(b1));
}
__device__ __forceinline__ void ldsm4(uint32_t r[4], uint32_t addr) {
    asm volatile("ldmatrix.sync.aligned.m8n8.x4.shared.b16 {%0,%1,%2,%3},[%4];"
        : "=r"(r[0]), "=r"(r[1]), "=r"(r[2]), "=r"(r[3]) : "r"(addr));
}
__device__ __forceinline__ void ldsm4t(uint32_t r[4], uint32_t addr) {
    asm volatile("ldmatrix.sync.aligned.m8n8.x4.trans.shared.b16 {%0,%1,%2,%3},[%4];"
        : "=r"(r[0]), "=r"(r[1]), "=r"(r[2]), "=r"(r[3]) : "r"(addr));
}
__device__ __forceinline__ void cpa16(uint32_t dst, const void* src) {
    asm volatile("cp.async.ca.shared.global [%0], [%1], 16;" :: "r"(dst), "l"(src));
}
__device__ __forceinline__ void cp_commit() {
    asm volatile("cp.async.commit_group;");
}
template<int N> __device__ __forceinline__ void cp_wait() {
    asm volatile("cp.async.wait_group %0;" :: "n"(N));
}

// ---------------------------------------------------------------------------
// QKV projection: C[4096,256] = X @ W + bias. Both X and W fp32 from params,
// register-prefetch double-buffered, fp16 at STS. Tile 64x64, 128 thr,
// k-step 32, 2 stages, ONE barrier per k-iter.
// z = 0/1/2 -> Q (scaled) / K ([d][l]) / V.
// ---------------------------------------------------------------------------
__global__ __launch_bounds__(128) void proj_qkv_kernel(
    const float* __restrict__ Xq, const float* __restrict__ Xk,
    const float* __restrict__ Xv,
    const float* __restrict__ Wq, const float* __restrict__ Wk,
    const float* __restrict__ Wv,
    const float* __restrict__ Bq, const float* __restrict__ Bk,
    const float* __restrict__ Bv)
{
    __shared__ __align__(16) __half Xs[2][64][40];   // 5120B/stage
    __shared__ __align__(16) __half Ws[2][32][72];   // 4608B/stage

    int z = blockIdx.z;
    const float* __restrict__ X    = (z == 0) ? Xq : (z == 1) ? Xk : Xv;
    const float* __restrict__ W    = (z == 0) ? Wq : (z == 1) ? Wk : Wv;
    const float* __restrict__ bias = (z == 0) ? Bq : (z == 1) ? Bk : Bv;

    int tid  = threadIdx.x;
    int lane = tid & 31, warp = tid >> 5;
    int gid  = lane >> 2, tig = lane & 3;
    int m0   = warp * 16;
    int rowBase = blockIdx.y * 64;
    int colBase = blockIdx.x * 64;

    uint32_t xs_base = (uint32_t)__cvta_generic_to_shared(&Xs[0][0][0]);
    uint32_t ws_base = (uint32_t)__cvta_generic_to_shared(&Ws[0][0][0]);

    // X tile 64x32 fp32 = 512 float4, 4/thread; W tile 32x64 fp32 = 512 float4
    auto ldgX = [&](float4 xr[4], int k0) {
        #pragma unroll
        for (int j = 0; j < 4; j++) {
            int i = tid + 128 * j;
            int r = i >> 3, c4 = i & 7;
            xr[j] = *(const float4*)&X[(size_t)(rowBase + r) * EMB + k0 + c4 * 4];
        }
    };
    auto stsX = [&](float4 xr[4], int s) {
        #pragma unroll
        for (int j = 0; j < 4; j++) {
            int i = tid + 128 * j;
            int r = i >> 3, c4 = i & 7;
            uint2 h; h.x = pack2(xr[j].x, xr[j].y); h.y = pack2(xr[j].z, xr[j].w);
            *(uint2*)&Xs[s][r][c4 * 4] = h;
        }
    };
    auto ldgW = [&](float4 wr[4], int k0) {
        #pragma unroll
        for (int j = 0; j < 4; j++) {
            int i = tid + 128 * j;
            int r = i >> 4, c4 = i & 15;
            wr[j] = *(const float4*)&W[(size_t)(k0 + r) * EMB + colBase + c4 * 4];
        }
    };
    auto stsW = [&](float4 wr[4], int s) {
        #pragma unroll
        for (int j = 0; j < 4; j++) {
            int i = tid + 128 * j;
            int r = i >> 4, c4 = i & 15;
            uint2 h; h.x = pack2(wr[j].x, wr[j].y); h.y = pack2(wr[j].z, wr[j].w);
            *(uint2*)&Ws[s][r][c4 * 4] = h;
        }
    };

    float cc[8][4];
    #pragma unroll
    for (int nn = 0; nn < 8; nn++)
        #pragma unroll
        for (int j = 0; j < 4; j++) cc[nn][j] = 0.f;

    float4 xr[4], wr[4];
    ldgX(xr, 0); ldgW(wr, 0);

    for (int it = 0; it < 8; it++) {
        int s = it & 1;
        stsX(xr, s); stsW(wr, s);
        if (it < 7) { ldgX(xr, (it + 1) * 32); ldgW(wr, (it + 1) * 32); }
        __syncthreads();   // stage s written by all; mma(it-2) on s proven done

        uint32_t xb = xs_base + s * 5120;
        uint32_t wb = ws_base + s * 4608;

        uint32_t a[2][4];
        #pragma unroll
        for (int kc = 0; kc < 2; kc++) {
            int m = lane >> 3;
            int row = m0 + (m & 1) * 8 + (lane & 7);
            int koff = kc * 16 + (m >> 1) * 8;
            ldsm4(a[kc], xb + row * 80 + koff * 2);
        }
        #pragma unroll
        for (int nn = 0; nn < 8; nn++) {
            uint32_t b[4];
            ldsm4t(b, wb + lane * 144 + nn * 16);
            mma_f16(cc[nn], a[0][0], a[0][1], a[0][2], a[0][3], b[0], b[1]);
            mma_f16(cc[nn], a[1][0], a[1][1], a[1][2], a[1][3], b[2], b[3]);
        }
    }

    // epilogue: scatter to g_Q / g_K / g_V
    int r_lo = rowBase + m0 + gid;
    int r_hi = r_lo + 8;
    #pragma unroll
    for (int nn = 0; nn < 8; nn++) {
        int c0 = colBase + nn * 8 + 2 * tig;
        float bv0 = bias[c0], bv1 = bias[c0 + 1];
        float v00 = cc[nn][0] + bv0, v01 = cc[nn][1] + bv1;   // row r_lo
        float v10 = cc[nn][2] + bv0, v11 = cc[nn][3] + bv1;   // row r_hi
        int h = (c0 >> 5) & 7, d = c0 & 31;
        int l0 = r_lo >> 1, b0i = r_lo & 1;     // row = l*B + b
        int l1 = r_hi >> 1, b1i = r_hi & 1;
        int bh0 = b0i * NH + h, bh1 = b1i * NH + h;
        if (z == 0) {
            g_Q[((size_t)bh0 * L_SEQ + l0) * (HD/2) + (d >> 1)] =
                __floats2half2_rn(v00 * SCALE_LOG2E, v01 * SCALE_LOG2E);
            g_Q[((size_t)bh1 * L_SEQ + l1) * (HD/2) + (d >> 1)] =
                __floats2half2_rn(v10 * SCALE_LOG2E, v11 * SCALE_LOG2E);
        } else if (z == 1) {
            g_K[((size_t)bh0 * HD + d    ) * L_SEQ + l0] = __float2half_rn(v00);
            g_K[((size_t)bh0 * HD + d + 1) * L_SEQ + l0] = __float2half_rn(v01);
            g_K[((size_t)bh1 * HD + d    ) * L_SEQ + l1] = __float2half_rn(v10);
            g_K[((size_t)bh1 * HD + d + 1) * L_SEQ + l1] = __float2half_rn(v11);
        } else {
            g_V[((size_t)bh0 * L_SEQ + l0) * (HD/2) + (d >> 1)] = __floats2half2_rn(v00, v01);
            g_V[((size_t)bh1 * L_SEQ + l1) * (HD/2) + (d >> 1)] = __floats2half2_rn(v10, v11);
        }
    }
}

// ---------------------------------------------------------------------------
// Flash attention: CTA = (b,h) x 128-query tile, 8 warps x 16 rows,
// 128-key tiles, 3-stage cp.async (dynamic smem), 1 barrier/iter.
// KV L2 traffic halved vs 64-row tiles. Output to g_AO fp16.
// Stage: Ks [32][136] (8704B) + Vs [128][40] (10240B) = 18944B.
// ---------------------------------------------------------------------------
#define ATTN_STAGE 18944
#define ATTN_SMEM  (3*ATTN_STAGE)

__global__ __launch_bounds__(256) void attn_kernel()
{
    extern __shared__ __align__(16) char sm_attn[];

    int bh = blockIdx.y;
    int q0 = blockIdx.x * QT;
    int tid  = threadIdx.x;
    int lane = tid & 31, warp = tid >> 5;
    int gid  = lane >> 2, tig = lane & 3;
    int m0   = warp * 16;

    const __half2* __restrict__ Qh = g_Q + (size_t)bh * L_SEQ * (HD/2);
    const __half*  __restrict__ Kp = g_K + (size_t)bh * HD * L_SEQ;
    const __half*  __restrict__ Vp = (const __half*)(g_V + (size_t)bh * L_SEQ * (HD/2));

    uint32_t smb = (uint32_t)__cvta_generic_to_shared(sm_attn);

    auto fill = [&](int s, int kt) {
        uint32_t kb = smb + s * ATTN_STAGE;
        uint32_t vb = kb + 8704;
        #pragma unroll
        for (int i = tid; i < 512; i += 256) {       // Ks[d][key]
            int d = i >> 4, c = i & 15;
            cpa16(kb + d * 272 + c * 16, Kp + (size_t)d * L_SEQ + kt + c * 8);
        }
        #pragma unroll
        for (int i = tid; i < 512; i += 256) {       // Vs[key][d]
            int key = i >> 2, c = i & 3;
            cpa16(vb + key * 80 + c * 16, Vp + (size_t)(kt + key) * HD + c * 8);
        }
    };

    // Q A-fragments from gmem (reused for all key tiles)
    uint32_t aq[2][4];
    #pragma unroll
    for (int kc = 0; kc < 2; kc++) {
        aq[kc][0] = *(const uint32_t*)&Qh[(size_t)(q0 + m0 + gid    ) * (HD/2) + kc * 8 + tig    ];
        aq[kc][1] = *(const uint32_t*)&Qh[(size_t)(q0 + m0 + gid + 8) * (HD/2) + kc * 8 + tig    ];
        aq[kc][2] = *(const uint32_t*)&Qh[(size_t)(q0 + m0 + gid    ) * (HD/2) + kc * 8 + tig + 4];
        aq[kc][3] = *(const uint32_t*)&Qh[(size_t)(q0 + m0 + gid + 8) * (HD/2) + kc * 8 + tig + 4];
    }

    float m_lo = -1e30f, m_hi = -1e30f, l_lo = 0.f, l_hi = 0.f;
    float oc[4][4];
    #pragma unroll
    for (int nf = 0; nf < 4; nf++)
        #pragma unroll
        for (int j = 0; j < 4; j++) oc[nf][j] = 0.f;

    fill(0, 0);   cp_commit();
    fill(1, KT);  cp_commit();

    const int NIT = L_SEQ / KT;   // 16
    for (int it = 0; it < NIT; it++) {
        if (it < NIT - 1) cp_wait<1>(); else cp_wait<0>();
        __syncthreads();                      // all warps done with iter it-1
        if (it < NIT - 2) { fill((it + 2) % 3, (it + 2) * KT); cp_commit(); }

        uint32_t kb = smb + (it % 3) * ATTN_STAGE;
        uint32_t vb = kb + 8704;

        // ---- S = Q K^T (logits in log2 domain via Q scale) ----
        float sc[16][4];
        #pragma unroll
        for (int nn = 0; nn < 16; nn++) {
            sc[nn][0] = sc[nn][1] = sc[nn][2] = sc[nn][3] = 0.f;
            uint32_t b[4];
            ldsm4t(b, kb + lane * 272 + nn * 16);
            mma_f16(sc[nn], aq[0][0], aq[0][1], aq[0][2], aq[0][3], b[0], b[1]);
            mma_f16(sc[nn], aq[1][0], aq[1][1], aq[1][2], aq[1][3], b[2], b[3]);
        }

        // ---- online softmax (exp2 domain) ----
        float mx_lo = -1e30f, mx_hi = -1e30f;
        #pragma unroll
        for (int nn = 0; nn < 16; nn++) {
            mx_lo = fmaxf(mx_lo, fmaxf(sc[nn][0], sc[nn][1]));
            mx_hi = fmaxf(mx_hi, fmaxf(sc[nn][2], sc[nn][3]));
        }
        mx_lo = fmaxf(mx_lo, __shfl_xor_sync(0xffffffffu, mx_lo, 1));
        mx_lo = fmaxf(mx_lo, __shfl_xor_sync(0xffffffffu, mx_lo, 2));
        mx_hi = fmaxf(mx_hi, __shfl_xor_sync(0xffffffffu, mx_hi, 1));
        mx_hi = fmaxf(mx_hi, __shfl_xor_sync(0xffffffffu, mx_hi, 2));

        float mn_lo = fmaxf(m_lo, mx_lo), mn_hi = fmaxf(m_hi, mx_hi);
        float al_lo = ex2(m_lo - mn_lo), al_hi = ex2(m_hi - mn_hi);
        m_lo = mn_lo; m_hi = mn_hi;

        float sum_lo = 0.f, sum_hi = 0.f;
        #pragma unroll
        for (int nn = 0; nn < 16; nn++) {
            float p0 = ex2(sc[nn][0] - mn_lo);
            float p1 = ex2(sc[nn][1] - mn_lo);
            float p2 = ex2(sc[nn][2] - mn_hi);
            float p3 = ex2(sc[nn][3] - mn_hi);
            sum_lo += p0 + p1;  sum_hi += p2 + p3;
            sc[nn][0] = p0; sc[nn][1] = p1; sc[nn][2] = p2; sc[nn][3] = p3;
        }
        sum_lo += __shfl_xor_sync(0xffffffffu, sum_lo, 1);
        sum_lo += __shfl_xor_sync(0xffffffffu, sum_lo, 2);
        sum_hi += __shfl_xor_sync(0xffffffffu, sum_hi, 1);
        sum_hi += __shfl_xor_sync(0xffffffffu, sum_hi, 2);
        l_lo = l_lo * al_lo + sum_lo;
        l_hi = l_hi * al_hi + sum_hi;

        #pragma unroll
        for (int nf = 0; nf < 4; nf++) {
            oc[nf][0] *= al_lo; oc[nf][1] *= al_lo;
            oc[nf][2] *= al_hi; oc[nf][3] *= al_hi;
        }

        // ---- O += P V ----
        #pragma unroll
        for (int kg = 0; kg < 4; kg++) {
            uint32_t pA0 = pack2(sc[4*kg    ][0], sc[4*kg    ][1]);
            uint32_t pA1 = pack2(sc[4*kg    ][2], sc[4*kg    ][3]);
            uint32_t pA2 = pack2(sc[4*kg + 1][0], sc[4*kg + 1][1]);
            uint32_t pA3 = pack2(sc[4*kg + 1][2], sc[4*kg + 1][3]);
            uint32_t pB0 = pack2(sc[4*kg + 2][0], sc[4*kg + 2][1]);
            uint32_t pB1 = pack2(sc[4*kg + 2][2], sc[4*kg + 2][3]);
            uint32_t pB2 = pack2(sc[4*kg + 3][0], sc[4*kg + 3][1]);
            uint32_t pB3 = pack2(sc[4*kg + 3][2], sc[4*kg + 3][3]);
            #pragma unroll
            for (int nf = 0; nf < 4; nf++) {
                uint32_t v[4];
                ldsm4t(v, vb + (kg * 32 + lane) * 80 + nf * 16);
                mma_f16(oc[nf], pA0, pA1, pA2, pA3, v[0], v[1]);
                mma_f16(oc[nf], pB0, pB1, pB2, pB3, v[2], v[3]);
            }
        }
    }

    // ---- normalize + store to g_AO [l][b][e/2] ----
    float inv_lo = 1.f / l_lo, inv_hi = 1.f / l_hi;
    int b = bh >> 3, h = bh & 7;
    int r_lo = q0 + m0 + gid, r_hi = r_lo + 8;
    #pragma unroll
    for (int nf = 0; nf < 4; nf++) {
        int c2 = h * 16 + nf * 4 + tig;
        g_AO[((size_t)r_lo * BATCH + b) * (EMB/2) + c2] =
            __floats2half2_rn(oc[nf][0] * inv_lo, oc[nf][1] * inv_lo);
        g_AO[((size_t)r_hi * BATCH + b) * (EMB/2) + c2] =
            __floats2half2_rn(oc[nf][2] * inv_hi, oc[nf][3] * inv_hi);
    }
}

// ---------------------------------------------------------------------------
// Output projection: out[4096,256] = g_AO @ Wp + bp (fp32 out).
// AO fp16 and Wp fp32 both via register double-buffer (Wp converted at STS).
// Tile 64x64, 128 thr, 2 stages, ONE barrier per k-iter.
// ---------------------------------------------------------------------------
__global__ __launch_bounds__(128) void proj_out_kernel(
    const float* __restrict__ Wp, const float* __restrict__ bias,
    float* __restrict__ Cout)
{
    __shared__ __align__(16) __half Xs[2][64][40];
    __shared__ __align__(16) __half Ws[2][32][72];

    int tid  = threadIdx.x;
    int lane = tid & 31, warp = tid >> 5;
    int gid  = lane >> 2, tig = lane & 3;
    int m0   = warp * 16;
    int rowBase = blockIdx.y * 64;
    int colBase = blockIdx.x * 64;

    uint32_t xs_base = (uint32_t)__cvta_generic_to_shared(&Xs[0][0][0]);
    uint32_t ws_base = (uint32_t)__cvta_generic_to_shared(&Ws[0][0][0]);

    // X: 64 rows x 16 half2 = 256 uint4 chunks, 2/thread
    auto ldgX = [&](uint4 xr[2], int k0) {
        #pragma unroll
        for (int j = 0; j < 2; j++) {
            int i = tid + 128 * j;
            int r = i >> 2, c = i & 3;
            xr[j] = *((const uint4*)(g_AO + (size_t)(rowBase + r) * (EMB/2) + (k0 >> 1)) + c);
        }
    };
    auto stsX = [&](uint4 xr[2], int s) {
        #pragma unroll
        for (int j = 0; j < 2; j++) {
            int i = tid + 128 * j;
            int r = i >> 2, c = i & 3;
            *(uint4*)&Xs[s][r][c * 8] = xr[j];
        }
    };
    auto ldgW = [&](float4 wr[4], int k0) {
        #pragma unroll
        for (int j = 0; j < 4; j++) {
            int i = tid + 128 * j;
            int r = i >> 4, c4 = i & 15;
            wr[j] = *(const float4*)&Wp[(size_t)(k0 + r) * EMB + colBase + c4 * 4];
        }
    };
    auto stsW = [&](float4 wr[4], int s) {
        #pragma unroll
        for (int j = 0; j < 4; j++) {
            int i = tid + 128 * j;
            int r = i >> 4, c4 = i & 15;
            uint2 h; h.x = pack2(wr[j].x, wr[j].y); h.y = pack2(wr[j].z, wr[j].w);
            *(uint2*)&Ws[s][r][c4 * 4] = h;
        }
    };

    float cc[8][4];
    #pragma unroll
    for (int nn = 0; nn < 8; nn++)
        #pragma unroll
        for (int j = 0; j < 4; j++) cc[nn][j] = 0.f;

    uint4  xr[2];
    float4 wr[4];
    ldgX(xr, 0); ldgW(wr, 0);

    for (int it = 0; it < 8; it++) {
        int s = it & 1;
        stsX(xr, s); stsW(wr, s);
        if (it < 7) { ldgX(xr, (it + 1) * 32); ldgW(wr, (it + 1) * 32); }
        __syncthreads();

        uint32_t xb = xs_base + s * 5120;
        uint32_t wb = ws_base + s * 4608;

        uint32_t a[2][4];
        #pragma unroll
        for (int kc = 0; kc < 2; kc++) {
            int m = lane >> 3;
            int row = m0 + (m & 1) * 8 + (lane & 7);
            int koff = kc * 16 + (m >> 1) * 8;
            ldsm4(a[kc], xb + row * 80 + koff * 2);
        }
        #pragma unroll
        for (int nn = 0; nn < 8; nn++) {
            uint32_t b[4];
            ldsm4t(b, wb + lane * 144 + nn * 16);
            mma_f16(cc[nn], a[0][0], a[0][1], a[0][2], a[0][3], b[0], b[1]);
            mma_f16(cc[nn], a[1][0], a[1][1], a[1][2], a[1][3], b[2], b[3]);
        }
    }

    int r_lo = rowBase + m0 + gid;
    int r_hi = r_lo + 8;
    #pragma unroll
    for (int nn = 0; nn < 8; nn++) {
        int c0 = colBase + nn * 8 + 2 * tig;
        float bv0 = bias[c0], bv1 = bias[c0 + 1];
        *(float2*)&Cout[(size_t)r_lo * EMB + c0] =
            make_float2(cc[nn][0] + bv0, cc[nn][1] + bv1);
        *(float2*)&Cout[(size_t)r_hi * EMB + c0] =
            make_float2(cc[nn][2] + bv0, cc[nn][3] + bv1);
    }
}

// ---------------------------------------------------------------------------
extern "C" void kernel_launch(void* const* d_in, const int* in_sizes, int n_in,
                              void* d_out, int out_size)
{
    const float* query = (const float*)d_in[0];
    const float* key_  = (const float*)d_in[1];
    const float* value = (const float*)d_in[2];
    const float* Wq = (const float*)d_in[3];
    const float* bq = (const float*)d_in[4];
    const float* Wk = (const float*)d_in[5];
    const float* bk = (const float*)d_in[6];
    const float* Wv = (const float*)d_in[7];
    const float* bv = (const float*)d_in[8];
    const float* Wp = (const float*)d_in[9];
    const float* bp = (const float*)d_in[10];
    float* out = (float*)d_out;

    // idempotent, host-side, capture-safe; no static guard
    cudaFuncSetAttribute(attn_kernel,
        cudaFuncAttributeMaxDynamicSharedMemorySize, ATTN_SMEM);

    dim3 gridQKV(EMB / 64, NROWS / 64, 3);    // (4, 64, 3)
    proj_qkv_kernel<<<gridQKV, 128>>>(query, key_, value,
                                      Wq, Wk, Wv, bq, bk, bv);

    dim3 gridA(L_SEQ / QT, BATCH * NH);       // (16, 16)
    attn_kernel<<<gridA, 256, ATTN_SMEM>>>();

    dim3 gridP(EMB / 64, NROWS / 64);         // (4, 64)
    proj_out_kernel<<<gridP, 128>>>(Wp, bp, out);
}